// round 8
// baseline (speedup 1.0000x reference)
#include <cuda_runtime.h>
#include <cuda_fp16.h>
#include <cstdint>

// Problem constants
#define B_   32
#define C_   192
#define H_   64
#define W_   64
#define OH_  32
#define OW_  32

// -------- device scratch (no mallocs allowed) --------
__device__ float g_psum[8][C_];
__device__ float g_pss[8][C_];
__device__ float g_scale[2][C_];
__device__ float g_shift[2][C_];
__device__ unsigned g_whf[2 * 9 * C_ * (C_ / 2)];         // f16x2 weights [br][tap][oc][ic/2]
__device__ unsigned g_abits[2][B_][H_][2][32][6];         // bits [br][b][y][par][j][wd]
__device__ float    g_sc[B_][C_][OH_][OW_];               // shared avgpool shortcut

// ---------------- PTX helpers (sm_80-compatible) ----------------
__device__ __forceinline__ uint32_t smem_to_u32(const void* p) {
    uint32_t a;
    asm("{ .reg .u64 t; cvta.to.shared.u64 t, %1; cvt.u32.u64 %0, t; }" : "=r"(a) : "l"(p));
    return a;
}
#define CP_ASYNC16(dst, src, sz) \
    asm volatile("cp.async.cg.shared.global [%0], [%1], 16, %2;" \
        :: "r"(dst), "l"(src), "r"(sz) : "memory")
#define CP_ASYNC8(dst, src, sz) \
    asm volatile("cp.async.ca.shared.global [%0], [%1], 8, %2;" \
        :: "r"(dst), "l"(src), "r"(sz) : "memory")
#define CP_COMMIT() asm volatile("cp.async.commit_group;" ::: "memory")
#define CP_WAIT1()  asm volatile("cp.async.wait_group 1;" ::: "memory")
#define CP_WAIT0()  asm volatile("cp.async.wait_group 0;" ::: "memory")
#define LDSM_X4(r, addr) \
    asm volatile("ldmatrix.sync.aligned.m8n8.x4.shared.b16 {%0,%1,%2,%3}, [%4];" \
        : "=r"((r)[0]), "=r"((r)[1]), "=r"((r)[2]), "=r"((r)[3]) : "r"(addr))
// f16 x f16 -> f16 accumulate (packed 2-reg C/D fragment)
#define MMA_F16(d, a, b0, b1) \
    asm volatile("mma.sync.aligned.m16n8k16.row.col.f16.f16.f16.f16 " \
        "{%0,%1}, {%2,%3,%4,%5}, {%6,%7}, {%0,%1};" \
        : "+r"((d)[0]), "+r"((d)[1]) \
        : "r"((a)[0]), "r"((a)[1]), "r"((a)[2]), "r"((a)[3]), "r"(b0), "r"(b1))
#define STS128(r0, r1, r2, r3, addr) \
    asm volatile("st.shared.v4.b32 [%0], {%1, %2, %3, %4};" \
        :: "r"(addr), "r"(r0), "r"(r1), "r"(r2), "r"(r3) : "memory")

// ================= K1: per-channel partial sums =================
__global__ void k_stats(const float* __restrict__ x) {
    int c = blockIdx.x;
    int s = blockIdx.y;
    int tid = threadIdx.x;
    float sm = 0.f, ss = 0.f;
    for (int b = 4 * s; b < 4 * s + 4; b++) {
        const float4* p = (const float4*)(x + ((size_t)(b * C_ + c)) * (H_ * W_));
#pragma unroll
        for (int i = tid; i < (H_ * W_) / 4; i += 256) {
            float4 v = p[i];
            sm += (v.x + v.y) + (v.z + v.w);
            ss += fmaf(v.x, v.x, v.y * v.y) + fmaf(v.z, v.z, v.w * v.w);
        }
    }
    __shared__ float sh1[256], sh2[256];
    sh1[tid] = sm; sh2[tid] = ss;
    __syncthreads();
    for (int st = 128; st > 0; st >>= 1) {
        if (tid < st) { sh1[tid] += sh1[tid + st]; sh2[tid] += sh2[tid + st]; }
        __syncthreads();
    }
    if (tid == 0) { g_psum[s][c] = sh1[0]; g_pss[s][c] = sh2[0]; }
}

// ================= K1b: finalize stats + thresholds =================
__global__ void k_scaleshift(const float* __restrict__ g1, const float* __restrict__ b1,
                             const float* __restrict__ g2, const float* __restrict__ b2) {
    int i = blockIdx.x * blockDim.x + threadIdx.x;
    if (i >= 2 * C_) return;
    int br = i / C_, c = i % C_;
    float s = 0.f, q = 0.f;
#pragma unroll
    for (int k = 0; k < 8; k++) { s += g_psum[k][c]; q += g_pss[k][c]; }
    const float invn = 1.f / (float)(B_ * H_ * W_);
    float mu = s * invn;
    float var = q * invn - mu * mu;
    float rstd = rsqrtf(var + 1e-5f);
    float gamma = br ? g2[c] : g1[c];
    float beta  = br ? b2[c] : b1[c];
    float sc = gamma * rstd;
    g_scale[br][c] = sc;
    g_shift[br][c] = beta - sc * mu;
}

// ================= K2: pack weights to f16 +-1, [br][tap][oc][ic] =========
__global__ void k_wpack(const float* __restrict__ w1, const float* __restrict__ w2) {
    int i = blockIdx.x * 256 + threadIdx.x;
    if (i >= 2 * 9 * C_ * (C_ / 2)) return;
    int cw = i % (C_ / 2);
    int t = i / (C_ / 2);
    int oc = t % C_; t /= C_;
    int tap = t % 9;
    int br = t / 9;
    int ky = tap / 3, kx = tap % 3;
    const float* w = br ? w2 : w1;
    int c0 = 2 * cw;
    float v0 = w[((oc * C_ + c0) * 3 + ky) * 3 + kx];
    float v1 = w[((oc * C_ + c0 + 1) * 3 + ky) * 3 + kx];
    unsigned lo = v0 > 0.f ? 0x3C00u : 0xBC00u;
    unsigned hi = v1 > 0.f ? 0x3C00u : 0xBC00u;
    g_whf[i] = lo | (hi << 16);
}

// ========== K3: fused binarize+pack (parity bit layout) + avgpool shortcut ==========
__global__ void __launch_bounds__(256) k_pack(const float* __restrict__ x) {
    __shared__ float s_scale[2 * C_], s_shift[2 * C_];
    int tid = threadIdx.x;
    for (int i = tid; i < 2 * C_; i += 256) {
        s_scale[i] = ((const float*)g_scale)[i];
        s_shift[i] = ((const float*)g_shift)[i];
    }
    __syncthreads();

    int gw = blockIdx.x * 8 + (tid >> 5);
    int lane = tid & 31;                 // = j (half-x index)
    int b = gw / (OH_ * 3);
    int rem = gw % (OH_ * 3);
    int oy = rem / 3;
    int wp = rem % 3;
    int c0 = wp * 64;

    const float* px = x + ((size_t)(b * C_ + c0)) * (H_ * W_) + (2 * oy) * W_ + 2 * lane;
    float* psc = &g_sc[b][c0][oy][lane];
    int y0 = 2 * oy;

    unsigned acc[2][8];
#pragma unroll
    for (int wdl = 0; wdl < 2; wdl++)
#pragma unroll
        for (int k = 0; k < 8; k++) acc[wdl][k] = 0;

#pragma unroll
    for (int wdl = 0; wdl < 2; wdl++) {
#pragma unroll 8
        for (int j = 0; j < 32; j++) {
            int cl = wdl * 32 + j;
            int c = c0 + cl;
            const float* pc = px + (size_t)cl * (H_ * W_);
            float2 r0 = *(const float2*)pc;
            float2 r1 = *(const float2*)(pc + W_);
            psc[(size_t)cl * (OH_ * OW_)] = (r0.x + r0.y + r1.x + r1.y) * 0.25f;
            float s0 = s_scale[c],      t0 = s_shift[c];
            float s1 = s_scale[C_ + c], t1 = s_shift[C_ + c];
            unsigned bit = 1u << j;
            if (fmaf(s0, r0.x, t0) > 0.f) acc[wdl][0] |= bit;
            if (fmaf(s0, r0.y, t0) > 0.f) acc[wdl][1] |= bit;
            if (fmaf(s0, r1.x, t0) > 0.f) acc[wdl][2] |= bit;
            if (fmaf(s0, r1.y, t0) > 0.f) acc[wdl][3] |= bit;
            if (fmaf(s1, r0.x, t1) > 0.f) acc[wdl][4] |= bit;
            if (fmaf(s1, r0.y, t1) > 0.f) acc[wdl][5] |= bit;
            if (fmaf(s1, r1.x, t1) > 0.f) acc[wdl][6] |= bit;
            if (fmaf(s1, r1.y, t1) > 0.f) acc[wdl][7] |= bit;
        }
    }

    // pixel p = (dy, dx): y = y0+dy, par = dx, j = lane
#pragma unroll
    for (int br = 0; br < 2; br++)
#pragma unroll
        for (int p = 0; p < 4; p++) {
            int dy = p >> 1, dx = p & 1;
            uint2 v = make_uint2(acc[0][br * 4 + p], acc[1][br * 4 + p]);
            *(uint2*)&g_abits[br][b][y0 + dy][dx][lane][2 * wp] = v;
        }
}

// ================= K4: f16 HMMA implicit-GEMM conv, pipelined =================
// CTA: M=128 pixels (4 oy x 32 ox), N=192 oc, K=9 taps x 192 ic.
// 512 threads = 16 warps (4M x 4N), warp tile 32x48.
// smem: A tile 128x400B (expanded per tap from resident bit patch),
//       B double buffer 2x192x400B (cp.async), bit patch 9x2x32 rows x 24B.
#define A_ST      400
#define A_BYTES   51200            // 128*400
#define BBUF_B    76800            // 192*400
#define PAT_ROWS  576              // 9*2*32
#define PAT_B     13824            // 576*24
#define PAT_OFF   (A_BYTES + 2 * BBUF_B)
#define CONV_SMEM (PAT_OFF + PAT_B)   // 218624

__global__ void __launch_bounds__(512, 1) k_conv(const float* __restrict__ bias1,
                                                 const float* __restrict__ bias2,
                                                 float* __restrict__ out) {
    extern __shared__ __align__(16) char smem[];
    __shared__ float s_bias[C_];
    uint32_t sb = smem_to_u32(smem);
    const uint32_t sbB0 = sb + A_BYTES;
    const uint32_t sbPAT = sb + PAT_OFF;

    int tid = threadIdx.x;
    int lane = tid & 31, w = tid >> 5;
    int wm = w & 3, wn = w >> 2;
    int yg = blockIdx.x, br = blockIdx.y, b = blockIdx.z;
    int oy0 = yg * 4;

    const float* bias = br ? bias2 : bias1;
    if (tid < C_) s_bias[tid] = bias[tid];

    const int8_t* gw8 = (const int8_t*)g_whf + (size_t)br * 9 * C_ * (C_ * 2);

    // ---- prologue: bit patch + B(0) into group 0 ----
    {
        const unsigned* gab = &g_abits[br][b][0][0][0][0];
        for (int i = tid; i < PAT_ROWS * 3; i += 512) {
            int row = i / 3, part = i - 3 * row;
            int ylocal = row >> 6;
            int rem = row & 63;
            int y = 2 * oy0 - 1 + ylocal;
            bool ok = (y >= 0);
            const int8_t* src = (const int8_t*)(gab + (ok ? ((y * 64 + rem) * 6) : 0)) + part * 8;
            CP_ASYNC8(sbPAT + (uint32_t)(row * 24 + part * 8), src, ok ? 8u : 0u);
        }
        for (int i = tid; i < 4608; i += 512) {
            int oc = i / 24, t = i - oc * 24;
            CP_ASYNC16(sbB0 + (uint32_t)(oc * A_ST + t * 16), gw8 + (size_t)oc * 384 + t * 16, 16u);
        }
        CP_COMMIT();
        CP_WAIT0();
        __syncthreads();
    }

    // ---- ldmatrix fragment geometry (verified in rounds 4/7) ----
    uint32_t a_addr[2];
#pragma unroll
    for (int mt = 0; mt < 2; mt++) {
        int row = wm * 32 + mt * 16 + (lane & 15);
        int col8 = (lane >> 4) * 8;
        a_addr[mt] = sb + (uint32_t)(row * A_ST + col8 * 2);
    }
    uint32_t boff[3];
    {
        int sub = lane & 7, gg = lane >> 3;
#pragma unroll
        for (int np = 0; np < 3; np++) {
            int row = wn * 48 + np * 16 + sub + ((gg >> 1) << 3);
            int kcol = (gg & 1) * 8;
            boff[np] = (uint32_t)(row * A_ST + kcol * 2);
        }
    }

    uint32_t d[2][6][2];   // packed f16x2 accumulators
#pragma unroll
    for (int mt = 0; mt < 2; mt++)
#pragma unroll
        for (int nt = 0; nt < 6; nt++) { d[mt][nt][0] = 0u; d[mt][nt][1] = 0u; }

    for (int tap = 0; tap < 9; tap++) {
        int ky = tap / 3, kx = tap - 3 * (tap / 3);

        // ---- expand A(tap): resident bits -> f16 {+1,-1,0} ----
#pragma unroll
        for (int i = tid; i < 768; i += 512) {
            int wd = i % 6, p = i / 6;
            int r = p >> 5, ox = p & 31;
            int y = 2 * (oy0 + r) + ky - 1;
            bool ok = (y >= 0) && !(kx == 0 && ox == 0);
            int par = (kx != 1) ? 1 : 0;
            int j = ox - (kx == 0);
            int jc = j < 0 ? 0 : j;
            uint32_t poff = sbPAT + (uint32_t)((((2 * r + ky) * 2 + par) * 32 + jc) * 24 + wd * 4);
            uint32_t bits;
            asm volatile("ld.shared.b32 %0, [%1];" : "=r"(bits) : "r"(poff));
            bits = ok ? bits : 0u;
            uint32_t base = ok ? 0xBC00BC00u : 0u;   // f16 -1,-1 (sign bit flips to +1)
            uint32_t dst = sb + (uint32_t)(p * A_ST + wd * 64);
#pragma unroll
            for (int q = 0; q < 4; q++) {
                uint32_t t = bits >> (8 * q);
                uint32_t v0 = base ^ ((t & 1u) << 15)        ^ ((t & 2u) << 30);
                uint32_t v1 = base ^ (((t >> 2) & 1u) << 15) ^ (((t >> 2) & 2u) << 30);
                uint32_t v2 = base ^ (((t >> 4) & 1u) << 15) ^ (((t >> 4) & 2u) << 30);
                uint32_t v3 = base ^ (((t >> 6) & 1u) << 15) ^ (((t >> 6) & 2u) << 30);
                STS128(v0, v1, v2, v3, dst + q * 16);
            }
        }

        // ---- issue B(tap+1) ----
        if (tap < 8) {
            const int8_t* gwn = gw8 + (size_t)(tap + 1) * C_ * 384;
            uint32_t dstB = sbB0 + ((tap + 1) & 1) * BBUF_B;
            for (int i = tid; i < 4608; i += 512) {
                int oc = i / 24, t = i - oc * 24;
                CP_ASYNC16(dstB + (uint32_t)(oc * A_ST + t * 16), gwn + (size_t)oc * 384 + t * 16, 16u);
            }
            CP_COMMIT();
            CP_WAIT1();   // B(tap) complete for this thread
        } else {
            CP_WAIT0();
        }
        __syncthreads();  // A(tap) stores + everyone's B(tap) landed

        uint32_t bbase = sbB0 + (tap & 1) * BBUF_B;
#pragma unroll
        for (int kc = 0; kc < 12; kc++) {
            uint32_t af[2][4];
#pragma unroll
            for (int mt = 0; mt < 2; mt++) LDSM_X4(af[mt], a_addr[mt] + kc * 32);
            uint32_t bf[3][4];
#pragma unroll
            for (int np = 0; np < 3; np++) LDSM_X4(bf[np], bbase + boff[np] + kc * 32);
#pragma unroll
            for (int mt = 0; mt < 2; mt++)
#pragma unroll
                for (int nt = 0; nt < 6; nt++) {
                    int np = nt >> 1;
                    if (nt & 1) { MMA_F16(d[mt][nt], af[mt], bf[np][2], bf[np][3]); }
                    else        { MMA_F16(d[mt][nt], af[mt], bf[np][0], bf[np][1]); }
                }
        }
        __syncthreads();  // A tile free for next expand
    }

    // ---- epilogue: transpose via smem, fuse bias+relu+shortcut, coalesced out ----
    float* S = (float*)smem;     // S[c][m], stride 132 floats
#pragma unroll
    for (int mt = 0; mt < 2; mt++)
#pragma unroll
        for (int nt = 0; nt < 6; nt++)
#pragma unroll
            for (int k = 0; k < 2; k++) {
                __half2 hv = *reinterpret_cast<__half2*>(&d[mt][nt][k]);
                float2 f = __half22float2(hv);
                int m = wm * 32 + mt * 16 + (lane >> 2) + (k << 3);
                int c = wn * 48 + nt * 8 + ((lane & 3) << 1);
                S[c * 132 + m] = f.x;
                S[(c + 1) * 132 + m] = f.y;
            }
    __syncthreads();

    size_t ob = ((size_t)b * (2 * C_) + (size_t)br * C_) * (OH_ * OW_) + (size_t)yg * 128;
    const float* scp = &g_sc[b][0][0][0] + yg * 128;
#pragma unroll
    for (int i = tid; i < 24576; i += 512) {
        int c = i >> 7, m = i & 127;
        float v = S[c * 132 + m] + s_bias[c];
        v = fmaxf(v, 0.f) + scp[(size_t)c * (OH_ * OW_) + m];
        out[ob + (size_t)c * (OH_ * OW_) + m] = v;
    }
}

// ================= launch =================
extern "C" void kernel_launch(void* const* d_in, const int* in_sizes, int n_in,
                              void* d_out, int out_size) {
    const float* x     = (const float*)d_in[0];
    const float* g1    = (const float*)d_in[1];
    const float* b1    = (const float*)d_in[2];
    const float* w1    = (const float*)d_in[3];
    const float* bias1 = (const float*)d_in[4];
    const float* g2    = (const float*)d_in[5];
    const float* b2    = (const float*)d_in[6];
    const float* w2    = (const float*)d_in[7];
    const float* bias2 = (const float*)d_in[8];
    float* out = (float*)d_out;

    cudaFuncSetAttribute(k_conv, cudaFuncAttributeMaxDynamicSharedMemorySize, CONV_SMEM);

    k_stats<<<dim3(C_, 8), 256>>>(x);
    k_scaleshift<<<2, C_>>>(g1, b1, g2, b2);
    k_wpack<<<(2 * 9 * C_ * (C_ / 2) + 255) / 256, 256>>>(w1, w2);
    k_pack<<<(B_ * OH_ * 3) / 8, 256>>>(x);
    dim3 gconv(OH_ / 4, 2, B_);
    k_conv<<<gconv, 512, CONV_SMEM>>>(bias1, bias2, out);
}

// round 9
// speedup vs baseline: 1.0151x; 1.0151x over previous
#include <cuda_runtime.h>
#include <cstdint>

// Problem constants
#define B_   32
#define C_   192
#define H_   64
#define W_   64
#define OH_  32
#define OW_  32

// -------- device scratch (no mallocs allowed) --------
__device__ float g_psum[16][C_];
__device__ float g_pss[16][C_];
__device__ unsigned g_wbf[2 * 9 * C_ * (C_ / 2)];         // bf16x2 weights [br][tap][oc][ic/2]
__device__ unsigned g_abits[2][6][B_][H_][2][32];         // bits [br][plane][b][y][par][j]
__device__ float    g_sc[B_][C_][OH_][OW_];               // shared avgpool shortcut

// ---------------- PTX helpers (sm_80-compatible) ----------------
__device__ __forceinline__ uint32_t smem_to_u32(const void* p) {
    uint32_t a;
    asm("{ .reg .u64 t; cvta.to.shared.u64 t, %1; cvt.u32.u64 %0, t; }" : "=r"(a) : "l"(p));
    return a;
}
#define CP_ASYNC16(dst, src, sz) \
    asm volatile("cp.async.cg.shared.global [%0], [%1], 16, %2;" \
        :: "r"(dst), "l"(src), "r"(sz) : "memory")
#define CP_COMMIT() asm volatile("cp.async.commit_group;" ::: "memory")
#define CP_WAIT1()  asm volatile("cp.async.wait_group 1;" ::: "memory")
#define CP_WAIT0()  asm volatile("cp.async.wait_group 0;" ::: "memory")
#define LDSM_X4(r, addr) \
    asm volatile("ldmatrix.sync.aligned.m8n8.x4.shared.b16 {%0,%1,%2,%3}, [%4];" \
        : "=r"((r)[0]), "=r"((r)[1]), "=r"((r)[2]), "=r"((r)[3]) : "r"(addr))
#define MMA16816(d, a, b0, b1) \
    asm volatile("mma.sync.aligned.m16n8k16.row.col.f32.bf16.bf16.f32 " \
        "{%0,%1,%2,%3}, {%4,%5,%6,%7}, {%8,%9}, {%0,%1,%2,%3};" \
        : "+f"((d)[0]), "+f"((d)[1]), "+f"((d)[2]), "+f"((d)[3]) \
        : "r"((a)[0]), "r"((a)[1]), "r"((a)[2]), "r"((a)[3]), "r"(b0), "r"(b1))
#define STS128(r0, r1, r2, r3, addr) \
    asm volatile("st.shared.v4.b32 [%0], {%1, %2, %3, %4};" \
        :: "r"(addr), "r"(r0), "r"(r1), "r"(r2), "r"(r3) : "memory")

// ================= K1: per-channel partial sums (16-way) =================
__global__ void k_stats(const float* __restrict__ x) {
    int c = blockIdx.x;
    int s = blockIdx.y;           // 0..15, 2 batches each
    int tid = threadIdx.x;
    float sm = 0.f, ss = 0.f;
    for (int b = 2 * s; b < 2 * s + 2; b++) {
        const float4* p = (const float4*)(x + ((size_t)(b * C_ + c)) * (H_ * W_));
#pragma unroll
        for (int i = tid; i < (H_ * W_) / 4; i += 256) {
            float4 v = p[i];
            sm += (v.x + v.y) + (v.z + v.w);
            ss += fmaf(v.x, v.x, v.y * v.y) + fmaf(v.z, v.z, v.w * v.w);
        }
    }
    __shared__ float sh1[256], sh2[256];
    sh1[tid] = sm; sh2[tid] = ss;
    __syncthreads();
    for (int st = 128; st > 0; st >>= 1) {
        if (tid < st) { sh1[tid] += sh1[tid + st]; sh2[tid] += sh2[tid + st]; }
        __syncthreads();
    }
    if (tid == 0) { g_psum[s][c] = sh1[0]; g_pss[s][c] = sh2[0]; }
}

// ================= K2: pack weights to bf16 +-1, [br][tap][oc][ic] =========
__global__ void k_wpack(const float* __restrict__ w1, const float* __restrict__ w2) {
    int i = blockIdx.x * 256 + threadIdx.x;
    if (i >= 2 * 9 * C_ * (C_ / 2)) return;
    int cw = i % (C_ / 2);
    int t = i / (C_ / 2);
    int oc = t % C_; t /= C_;
    int tap = t % 9;
    int br = t / 9;
    int ky = tap / 3, kx = tap % 3;
    const float* w = br ? w2 : w1;
    int c0 = 2 * cw;
    float v0 = w[((oc * C_ + c0) * 3 + ky) * 3 + kx];
    float v1 = w[((oc * C_ + c0 + 1) * 3 + ky) * 3 + kx];
    unsigned lo = v0 > 0.f ? 0x3F80u : 0xBF80u;
    unsigned hi = v1 > 0.f ? 0x3F80u : 0xBF80u;
    g_wbf[i] = lo | (hi << 16);
}

// ========== K3: fused stats-finalize + binarize (plane layout) + avgpool ==========
// 6144 warps: warp = (b, oy, wp), wp = 32-channel group = bit plane.
__global__ void __launch_bounds__(256) k_pack(const float* __restrict__ x,
                                              const float* __restrict__ g1,
                                              const float* __restrict__ b1,
                                              const float* __restrict__ g2,
                                              const float* __restrict__ b2) {
    __shared__ float s_scale[2 * C_], s_shift[2 * C_];
    int tid = threadIdx.x;
    for (int i = tid; i < 2 * C_; i += 256) {
        int br = i / C_, c = i % C_;
        float s = 0.f, q = 0.f;
#pragma unroll
        for (int k = 0; k < 16; k++) { s += g_psum[k][c]; q += g_pss[k][c]; }
        const float invn = 1.f / (float)(B_ * H_ * W_);
        float mu = s * invn;
        float var = q * invn - mu * mu;
        float rstd = rsqrtf(var + 1e-5f);
        float gamma = br ? g2[c] : g1[c];
        float beta  = br ? b2[c] : b1[c];
        float sc = gamma * rstd;
        s_scale[i] = sc;
        s_shift[i] = beta - sc * mu;
    }
    __syncthreads();

    int gw = blockIdx.x * 8 + (tid >> 5);   // 0..6143
    int lane = tid & 31;                    // = j (half-x index)
    int b = gw / (OH_ * 6);
    int rem = gw % (OH_ * 6);
    int oy = rem / 6;
    int wp = rem % 6;                       // 32-channel plane
    int c0 = wp * 32;

    const float* px = x + ((size_t)(b * C_ + c0)) * (H_ * W_) + (2 * oy) * W_ + 2 * lane;
    float* psc = &g_sc[b][c0][oy][lane];
    int y0 = 2 * oy;

    unsigned acc[8];                        // br*4 + pixel(00,01,10,11)
#pragma unroll
    for (int k = 0; k < 8; k++) acc[k] = 0;

#pragma unroll 8
    for (int j = 0; j < 32; j++) {
        int c = c0 + j;
        const float* pc = px + (size_t)j * (H_ * W_);
        float2 r0 = *(const float2*)pc;
        float2 r1 = *(const float2*)(pc + W_);
        psc[(size_t)j * (OH_ * OW_)] = (r0.x + r0.y + r1.x + r1.y) * 0.25f;
        float s0 = s_scale[c],      t0 = s_shift[c];
        float s1 = s_scale[C_ + c], t1 = s_shift[C_ + c];
        unsigned bit = 1u << j;
        if (fmaf(s0, r0.x, t0) > 0.f) acc[0] |= bit;
        if (fmaf(s0, r0.y, t0) > 0.f) acc[1] |= bit;
        if (fmaf(s0, r1.x, t0) > 0.f) acc[2] |= bit;
        if (fmaf(s0, r1.y, t0) > 0.f) acc[3] |= bit;
        if (fmaf(s1, r0.x, t1) > 0.f) acc[4] |= bit;
        if (fmaf(s1, r0.y, t1) > 0.f) acc[5] |= bit;
        if (fmaf(s1, r1.x, t1) > 0.f) acc[6] |= bit;
        if (fmaf(s1, r1.y, t1) > 0.f) acc[7] |= bit;
    }

    // coalesced: lane j writes word j of [br][wp][b][y][par] row
#pragma unroll
    for (int br = 0; br < 2; br++)
#pragma unroll
        for (int p = 0; p < 4; p++) {
            int dy = p >> 1, dx = p & 1;
            g_abits[br][wp][b][y0 + dy][dx][lane] = acc[br * 4 + p];
        }
}

// ================= K4: bf16 HMMA implicit-GEMM conv, pipelined =================
// CTA: M=128 pixels (4 oy x 32 ox), N=192 oc, K=9 taps x 192 ic.
// 512 threads = 16 warps (4M x 4N), warp tile 32x48.
// smem: A tile 128x400B (expanded per tap from resident bit patch),
//       B double buffer 2x192x400B (cp.async), bit patch 6 planes x 9 rows x 256B.
#define A_ST      400
#define A_BYTES   51200            // 128*400
#define BBUF_B    76800            // 192*400
#define PAT_B     13824            // 6*9*256
#define PAT_OFF   (A_BYTES + 2 * BBUF_B)
#define CONV_SMEM (PAT_OFF + PAT_B)   // 218624

__global__ void __launch_bounds__(512, 1) k_conv(const float* __restrict__ bias1,
                                                 const float* __restrict__ bias2,
                                                 float* __restrict__ out) {
    extern __shared__ __align__(16) char smem[];
    __shared__ float s_bias[C_];
    uint32_t sb = smem_to_u32(smem);
    const uint32_t sbB0 = sb + A_BYTES;
    const uint32_t sbPAT = sb + PAT_OFF;

    int tid = threadIdx.x;
    int lane = tid & 31, w = tid >> 5;
    int wm = w & 3, wn = w >> 2;
    int yg = blockIdx.x, br = blockIdx.y, b = blockIdx.z;
    int oy0 = yg * 4;

    const float* bias = br ? bias2 : bias1;
    if (tid < C_) s_bias[tid] = bias[tid];

    const int8_t* gw8 = (const int8_t*)g_wbf + (size_t)br * 9 * C_ * (C_ * 2);

    // ---- prologue: bit patch (plane-major rows) + B(0) into group 0 ----
    {
        for (int i = tid; i < 864; i += 512) {
            int wd = i / 144;
            int r = i - wd * 144;
            int ylocal = r / 16;            // 0..8
            int t = r - ylocal * 16;        // 16B chunk within 256B row
            int y = 2 * oy0 - 1 + ylocal;
            bool ok = (y >= 0);
            const unsigned* base = &g_abits[br][wd][b][ok ? y : 0][0][0];
            CP_ASYNC16(sbPAT + (uint32_t)((wd * 9 + ylocal) * 256 + t * 16),
                       (const int8_t*)base + t * 16, ok ? 16u : 0u);
        }
        for (int i = tid; i < 4608; i += 512) {
            int oc = i / 24, t = i - oc * 24;
            CP_ASYNC16(sbB0 + (uint32_t)(oc * A_ST + t * 16), gw8 + (size_t)oc * 384 + t * 16, 16u);
        }
        CP_COMMIT();
        CP_WAIT0();
        __syncthreads();
    }

    // ---- ldmatrix fragment geometry (verified rounds 4-8) ----
    uint32_t a_addr[2];
#pragma unroll
    for (int mt = 0; mt < 2; mt++) {
        int row = wm * 32 + mt * 16 + (lane & 15);
        int col8 = (lane >> 4) * 8;
        a_addr[mt] = sb + (uint32_t)(row * A_ST + col8 * 2);
    }
    uint32_t boff[3];
    {
        int sub = lane & 7, gg = lane >> 3;
#pragma unroll
        for (int np = 0; np < 3; np++) {
            int row = wn * 48 + np * 16 + sub + ((gg >> 1) << 3);
            int kcol = (gg & 1) * 8;
            boff[np] = (uint32_t)(row * A_ST + kcol * 2);
        }
    }

    float d[2][6][4];
#pragma unroll
    for (int mt = 0; mt < 2; mt++)
#pragma unroll
        for (int nt = 0; nt < 6; nt++)
#pragma unroll
            for (int e = 0; e < 4; e++) d[mt][nt][e] = 0.f;

    for (int tap = 0; tap < 9; tap++) {
        int ky = tap / 3, kx = tap - 3 * (tap / 3);

        // ---- expand A(tap): resident bits -> bf16 {+1,-1,0} ----
#pragma unroll
        for (int i = tid; i < 768; i += 512) {
            int wd = i % 6, p = i / 6;
            int r = p >> 5, ox = p & 31;
            int y = 2 * (oy0 + r) + ky - 1;
            bool ok = (y >= 0) && !(kx == 0 && ox == 0);
            int par = (kx != 1) ? 1 : 0;
            int j = ox - (kx == 0);
            int jc = j < 0 ? 0 : j;
            uint32_t poff = sbPAT + (uint32_t)((wd * 9 + (2 * r + ky)) * 256 + ((par << 5) + jc) * 4);
            uint32_t bits;
            asm volatile("ld.shared.b32 %0, [%1];" : "=r"(bits) : "r"(poff));
            bits = ok ? bits : 0u;
            uint32_t base = ok ? 0xBF80BF80u : 0u;
            uint32_t dst = sb + (uint32_t)(p * A_ST + wd * 64);
#pragma unroll
            for (int q = 0; q < 4; q++) {
                uint32_t t = bits >> (8 * q);
                uint32_t v0 = base ^ ((t & 1u) << 15)        ^ ((t & 2u) << 30);
                uint32_t v1 = base ^ (((t >> 2) & 1u) << 15) ^ (((t >> 2) & 2u) << 30);
                uint32_t v2 = base ^ (((t >> 4) & 1u) << 15) ^ (((t >> 4) & 2u) << 30);
                uint32_t v3 = base ^ (((t >> 6) & 1u) << 15) ^ (((t >> 6) & 2u) << 30);
                STS128(v0, v1, v2, v3, dst + q * 16);
            }
        }

        // ---- issue B(tap+1) ----
        if (tap < 8) {
            const int8_t* gwn = gw8 + (size_t)(tap + 1) * C_ * 384;
            uint32_t dstB = sbB0 + ((tap + 1) & 1) * BBUF_B;
            for (int i = tid; i < 4608; i += 512) {
                int oc = i / 24, t = i - oc * 24;
                CP_ASYNC16(dstB + (uint32_t)(oc * A_ST + t * 16), gwn + (size_t)oc * 384 + t * 16, 16u);
            }
            CP_COMMIT();
            CP_WAIT1();
        } else {
            CP_WAIT0();
        }
        __syncthreads();

        uint32_t bbase = sbB0 + (tap & 1) * BBUF_B;
#pragma unroll
        for (int kc = 0; kc < 12; kc++) {
            uint32_t af[2][4];
#pragma unroll
            for (int mt = 0; mt < 2; mt++) LDSM_X4(af[mt], a_addr[mt] + kc * 32);
            uint32_t bf[3][4];
#pragma unroll
            for (int np = 0; np < 3; np++) LDSM_X4(bf[np], bbase + boff[np] + kc * 32);
#pragma unroll
            for (int mt = 0; mt < 2; mt++)
#pragma unroll
                for (int nt = 0; nt < 6; nt++) {
                    int np = nt >> 1;
                    if (nt & 1) { MMA16816(d[mt][nt], af[mt], bf[np][2], bf[np][3]); }
                    else        { MMA16816(d[mt][nt], af[mt], bf[np][0], bf[np][1]); }
                }
        }
        __syncthreads();
    }

    // ---- epilogue: transpose via smem, fuse bias+relu+shortcut, coalesced out ----
    float* S = (float*)smem;     // S[c][m], stride 132 floats
#pragma unroll
    for (int mt = 0; mt < 2; mt++)
#pragma unroll
        for (int nt = 0; nt < 6; nt++)
#pragma unroll
            for (int e = 0; e < 4; e++) {
                int m = wm * 32 + mt * 16 + (lane >> 2) + ((e >> 1) << 3);
                int c = wn * 48 + nt * 8 + ((lane & 3) << 1) + (e & 1);
                S[c * 132 + m] = d[mt][nt][e];
            }
    __syncthreads();

    size_t ob = ((size_t)b * (2 * C_) + (size_t)br * C_) * (OH_ * OW_) + (size_t)yg * 128;
    const float* scp = &g_sc[b][0][0][0] + yg * 128;
#pragma unroll
    for (int i = tid; i < 24576; i += 512) {
        int c = i >> 7, m = i & 127;
        float v = S[c * 132 + m] + s_bias[c];
        v = fmaxf(v, 0.f) + scp[(size_t)c * (OH_ * OW_) + m];
        out[ob + (size_t)c * (OH_ * OW_) + m] = v;
    }
}

// ================= launch =================
extern "C" void kernel_launch(void* const* d_in, const int* in_sizes, int n_in,
                              void* d_out, int out_size) {
    const float* x     = (const float*)d_in[0];
    const float* g1    = (const float*)d_in[1];
    const float* b1    = (const float*)d_in[2];
    const float* w1    = (const float*)d_in[3];
    const float* bias1 = (const float*)d_in[4];
    const float* g2    = (const float*)d_in[5];
    const float* b2    = (const float*)d_in[6];
    const float* w2    = (const float*)d_in[7];
    const float* bias2 = (const float*)d_in[8];
    float* out = (float*)d_out;

    cudaFuncSetAttribute(k_conv, cudaFuncAttributeMaxDynamicSharedMemorySize, CONV_SMEM);

    k_stats<<<dim3(C_, 16), 256>>>(x);
    k_wpack<<<(2 * 9 * C_ * (C_ / 2) + 255) / 256, 256>>>(w1, w2);
    k_pack<<<(B_ * OH_ * 6) / 8, 256>>>(x, g1, b1, g2, b2);
    dim3 gconv(OH_ / 4, 2, B_);
    k_conv<<<gconv, 512, CONV_SMEM>>>(bias1, bias2, out);
}